// round 14
// baseline (speedup 1.0000x reference)
#include <cuda_runtime.h>
#include <cuda_fp16.h>
#include <cstdint>

// ======================= problem constants =======================
#define BATCH 64
#define WDIM  513
#define CDIM  512
#define PLANE_ELEMS (BATCH * WDIM * CDIM)   // 16,809,984
#define NGROUP 4
#define GBATCH (BATCH / NGROUP)             // 16 batches per group

// fp16 planes of the L2-normalized inputs (scratch, ~67 MB)
__device__ __half g_h1[PLANE_ELEMS];
__device__ __half g_h2[PLANE_ELEMS];

// ======================= helpers =======================
__device__ __forceinline__ uint32_t smem_u32(const void* p) {
    uint32_t a;
    asm("{ .reg .u64 t; cvta.to.shared.u64 t, %1; cvt.u32.u64 %0, t; }" : "=r"(a) : "l"(p));
    return a;
}

#define CP_ASYNC16(dst, src) \
    asm volatile("cp.async.cg.shared.global [%0], [%1], 16;" :: "r"(dst), "l"(src) : "memory")
#define CP_COMMIT() asm volatile("cp.async.commit_group;" ::: "memory")
#define CP_WAIT(n)  asm volatile("cp.async.wait_group %0;" :: "n"(n) : "memory")

__device__ __forceinline__ void mma16816(float* d, uint32_t a0, uint32_t a1, uint32_t a2,
                                         uint32_t a3, uint32_t b0, uint32_t b1) {
    asm volatile(
        "mma.sync.aligned.m16n8k16.row.col.f32.f16.f16.f32 "
        "{%0,%1,%2,%3}, {%4,%5,%6,%7}, {%8,%9}, {%0,%1,%2,%3};"
        : "+f"(d[0]), "+f"(d[1]), "+f"(d[2]), "+f"(d[3])
        : "r"(a0), "r"(a1), "r"(a2), "r"(a3), "r"(b0), "r"(b1));
}

__device__ __forceinline__ void ldsm_x4(uint32_t* r, uint32_t addr) {
    asm volatile("ldmatrix.sync.aligned.m8n8.x4.shared.b16 {%0,%1,%2,%3}, [%4];"
                 : "=r"(r[0]), "=r"(r[1]), "=r"(r[2]), "=r"(r[3]) : "r"(addr));
}

// ======================= kernel 1: fused normalize + fp16 quantize (per group) =========
// grid (16, 2, 8): batch-in-group, tensor, 64-channel block. 256 thr = 32 ch-pairs x 8 W-slices.
__global__ void __launch_bounds__(256) prep_kernel(const float* __restrict__ x1,
                                                   const float* __restrict__ x2, int b0) {
    __shared__ float2 red[8][32];
    __shared__ float2 sinv[32];
    const int b = b0 + blockIdx.x, which = blockIdx.y, cb = blockIdx.z;
    const float* in = which ? x2 : x1;
    __half* hp = which ? g_h2 : g_h1;

    const int cp = threadIdx.x & 31;          // channel pair within block
    const int sl = threadIdx.x >> 5;          // W slice (0..7)
    const int c  = (cb << 6) + (cp << 1);     // absolute channel (even)
    const int w0 = sl * 65;
    const int w1 = (w0 + 65 < WDIM) ? (w0 + 65) : WDIM;
    const size_t base = (size_t)b * WDIM * CDIM + c;

    float s0 = 0.0f, s1 = 0.0f;
    for (int w = w0; w < w1; ++w) {
        float2 v = *(const float2*)(in + base + (size_t)w * CDIM);
        s0 = fmaf(v.x, v.x, s0);
        s1 = fmaf(v.y, v.y, s1);
    }
    red[sl][cp] = make_float2(s0, s1);
    __syncthreads();
    if (threadIdx.x < 32) {
        float a0 = 0.0f, a1 = 0.0f;
#pragma unroll
        for (int s = 0; s < 8; ++s) { a0 += red[s][threadIdx.x].x; a1 += red[s][threadIdx.x].y; }
        sinv[threadIdx.x] = make_float2(rsqrtf(fmaxf(a0, 1e-12f)), rsqrtf(fmaxf(a1, 1e-12f)));
    }
    __syncthreads();
    const float2 iv = sinv[cp];

    for (int w = w0; w < w1; ++w) {
        const size_t idx = base + (size_t)w * CDIM;
        float2 v = *(const float2*)(in + idx);
        *(__half2*)(hp + idx) = __floats2half2_rn(v.x * iv.x, v.y * iv.y);
    }
}

// ======================= kernel 2: strips from fp16 planes (out pre-zeroed) ============
// grid (64, 4): batch, quarter. All contributions via atomicAdd.
__global__ void __launch_bounds__(256) strip_kernel(float* __restrict__ out) {
    __shared__ float2 p1v[256], p2v[256];
    const int b = blockIdx.x, qr = blockIdx.y;
    const int tid = threadIdx.x;
    const int wid = tid >> 5, lane = tid & 31;
    const size_t rbase = (size_t)b * WDIM * CDIM;

    p1v[tid] = __half22float2(((const __half2*)(g_h1 + rbase + (size_t)512 * CDIM))[tid]);
    p2v[tid] = __half22float2(((const __half2*)(g_h2 + rbase + (size_t)512 * CDIM))[tid]);
    __syncthreads();

    // part 1: j = 512 fixed:  out[(768-w') % 513] += <p1, x2n[w',:]>,  w' in quarter
    {
        const int w0 = qr * 129, w1 = (w0 + 129 < WDIM) ? (w0 + 129) : WDIM;
        for (int wp = w0 + wid; wp < w1; wp += 8) {
            const float4* row = (const float4*)(g_h2 + rbase + (size_t)wp * CDIM);
            float s = 0.0f;
#pragma unroll
            for (int k = 0; k < 2; ++k) {
                const int i = lane + (k << 5);          // float4 index (8 halves), 0..63
                float4 r4 = row[i];
                const __half2* h = (const __half2*)&r4;
#pragma unroll
                for (int j = 0; j < 4; ++j) {
                    float2 f = __half22float2(h[j]);
                    float2 p = p1v[i * 4 + j];
                    s = fmaf(f.x, p.x, fmaf(f.y, p.y, s));
                }
            }
            for (int o = 16; o; o >>= 1) s += __shfl_xor_sync(0xFFFFFFFFu, s, o);
            if (lane == 0) atomicAdd(&out[(size_t)b * WDIM + (768 - wp) % WDIM], s);
        }
    }
    // part 2: w' = 512 fixed:  out[(j+257) % 513] += <p2, x1n[j,:]>,  j in quarter (0..511)
    {
        const int j0 = qr * 128, j1 = j0 + 128;
        for (int j = j0 + wid; j < j1; j += 8) {
            const float4* row = (const float4*)(g_h1 + rbase + (size_t)j * CDIM);
            float s = 0.0f;
#pragma unroll
            for (int k = 0; k < 2; ++k) {
                const int i = lane + (k << 5);
                float4 r4 = row[i];
                const __half2* h = (const __half2*)&r4;
#pragma unroll
                for (int jj = 0; jj < 4; ++jj) {
                    float2 f = __half22float2(h[jj]);
                    float2 p = p2v[i * 4 + jj];
                    s = fmaf(f.x, p.x, fmaf(f.y, p.y, s));
                }
            }
            for (int o = 16; o; o >>= 1) s += __shfl_xor_sync(0xFFFFFFFFu, s, o);
            if (lane == 0) atomicAdd(&out[(size_t)b * WDIM + (j + 257) % WDIM], s);
        }
    }
}

// ======================= kernel 3: fp16 mma.sync GEMM, K = 512 (per group) ==========
// CTA: 128(M=j) x 128(N=w') Gram tile; 8 chunks of 64 halves, 3-stage cp.async.
// 256 threads = 8 warps (4M x 2N), warp tile 32x64. grid = 16 batches x 16 tiles.
#define NCHUNKS  8                     // 512 / 64
#define STAGE    32768                 // A 16KB + B 16KB (128 rows x 128B each)
#define NSTAGE   3
#define CPITCH   130
#define SMEM_GEMM (NSTAGE * STAGE)     // 98304 >= epilogue 128*130*4 = 66560

__global__ void __launch_bounds__(256, 2) gemm_kernel(float* __restrict__ out, int b0) {
    extern __shared__ char sm[];
    const uint32_t sb = smem_u32(sm);

    const int tid  = threadIdx.x;
    const int lane = tid & 31, warp = tid >> 5;
    const int wm = warp >> 1, wn = warp & 1;       // warp grid 4(M) x 2(N)
    const int l15 = lane & 15;

    const int b  = b0 + (blockIdx.x >> 4);
    const int j0 = ((blockIdx.x >> 2) & 3) << 7;
    const int n0 = (blockIdx.x & 3) << 7;

    float acc[2][8][4];
#pragma unroll
    for (int mt = 0; mt < 2; ++mt)
#pragma unroll
        for (int nt = 0; nt < 8; ++nt)
#pragma unroll
            for (int i = 0; i < 4; ++i) acc[mt][nt][i] = 0.0f;

    // O(1)-register loader bases (swizzle is q-invariant: row steps by 32 per q)
    const int lr = tid >> 3, lc = tid & 7;
    const uint32_t dOff0 = (uint32_t)((lr << 7) + ((lc ^ (lr & 7)) << 4));
    const uint32_t sOff0 = (uint32_t)(lr * CDIM + (lc << 3));
    const __half* pA = g_h1 + ((size_t)(b * WDIM + j0)) * CDIM + sOff0;
    const __half* pB = g_h2 + ((size_t)(b * WDIM + n0)) * CDIM + sOff0;

    // per-lane ldmatrix address components (row base * 128B + swizzled 16B chunk)
    uint32_t offk[4];
#pragma unroll
    for (int ks = 0; ks < 4; ++ks)
        offk[ks] = (uint32_t)((((ks << 1) | (lane >> 4)) ^ (lane & 7)) << 4);
    uint32_t arow[2], brow[4];
#pragma unroll
    for (int mt = 0; mt < 2; ++mt) arow[mt] = (uint32_t)((wm * 32 + mt * 16 + l15) << 7);
#pragma unroll
    for (int ng = 0; ng < 4; ++ng) brow[ng] = (uint32_t)((wn * 64 + ng * 16 + l15) << 7);

    // async chunk loader: 64 halves of K (128B/row), XOR-swizzled 16B chunks
    auto load_chunk = [&](int k, int s) {
        const uint32_t c0 = k << 6;
        const uint32_t sA = sb + s * STAGE + dOff0;
        const uint32_t sB = sA + 16384;
#pragma unroll
        for (int q = 0; q < 4; ++q) CP_ASYNC16(sA + q * 4096, pA + c0 + q * (32 * CDIM));
#pragma unroll
        for (int q = 0; q < 4; ++q) CP_ASYNC16(sB + q * 4096, pB + c0 + q * (32 * CDIM));
        CP_COMMIT();
    };

    load_chunk(0, 0);
    load_chunk(1, 1);

    int st = 0, ls = 2;
    for (int k = 0; k < NCHUNKS; ++k) {
        if (k < NCHUNKS - 1) { CP_WAIT(1); } else { CP_WAIT(0); }
        __syncthreads();
        if (k + 2 < NCHUNKS) load_chunk(k + 2, ls);

        const uint32_t sA = sb + st * STAGE;
        const uint32_t sB = sA + 16384;
#pragma unroll
        for (int ks = 0; ks < 4; ++ks) {
            uint32_t a0[4], a1[4];
            ldsm_x4(a0, sA + arow[0] + offk[ks]);
            ldsm_x4(a1, sA + arow[1] + offk[ks]);
#pragma unroll
            for (int ng = 0; ng < 4; ++ng) {
                uint32_t q[4];
                ldsm_x4(q, sB + brow[ng] + offk[ks]);
                mma16816(acc[0][ng * 2],     a0[0], a0[1], a0[2], a0[3], q[0], q[2]);
                mma16816(acc[0][ng * 2 + 1], a0[0], a0[1], a0[2], a0[3], q[1], q[3]);
                mma16816(acc[1][ng * 2],     a1[0], a1[1], a1[2], a1[3], q[0], q[2]);
                mma16816(acc[1][ng * 2 + 1], a1[0], a1[1], a1[2], a1[3], q[1], q[3]);
            }
        }
        st = (st == NSTAGE - 1) ? 0 : st + 1;
        ls = (ls == NSTAGE - 1) ? 0 : ls + 1;
    }

    // --- epilogue: stage C in smem, fold diagonals, atomicAdd to global ---
    __syncthreads();
    float* C = (float*)sm;
    const int g = lane >> 2, t4 = lane & 3;
#pragma unroll
    for (int mt = 0; mt < 2; ++mt) {
        const int r0 = wm * 32 + mt * 16 + g;
#pragma unroll
        for (int nt = 0; nt < 8; ++nt) {
            const int c = wn * 64 + nt * 8 + 2 * t4;
            C[r0 * CPITCH + c]           = acc[mt][nt][0];
            C[r0 * CPITCH + c + 1]       = acc[mt][nt][1];
            C[(r0 + 8) * CPITCH + c]     = acc[mt][nt][2];
            C[(r0 + 8) * CPITCH + c + 1] = acc[mt][nt][3];
        }
    }
    __syncthreads();

    if (tid < 255) {
        const int d = tid - 127;                 // diag offset r - c
        float s = 0.0f;
#pragma unroll 4
        for (int r = 0; r < 128; ++r) {
            const int c = r - d;
            if (c >= 0 && c < 128) s += C[r * CPITCH + c];
        }
        const int widx = (j0 - n0 + d + 256 + 1026) % WDIM;
        atomicAdd(&out[(size_t)b * WDIM + widx], s);
    }
}

// ======================= launch: 2-stream pipelined groups =======================
extern "C" void kernel_launch(void* const* d_in, const int* in_sizes, int n_in,
                              void* d_out, int out_size) {
    const float* x1 = (const float*)d_in[0];
    const float* x2 = (const float*)d_in[1];
    float* out = (float*)d_out;

    // one-time plumbing (created on the correctness call, outside graph capture;
    // no device memory is allocated by streams/events)
    static cudaStream_t s1 = nullptr;
    static cudaEvent_t evP[NGROUP], evEnd;
    if (s1 == nullptr) {
        cudaStreamCreateWithFlags(&s1, cudaStreamNonBlocking);
        for (int g = 0; g < NGROUP; ++g)
            cudaEventCreateWithFlags(&evP[g], cudaEventDisableTiming);
        cudaEventCreateWithFlags(&evEnd, cudaEventDisableTiming);
        cudaFuncSetAttribute(gemm_kernel, cudaFuncAttributeMaxDynamicSharedMemorySize, SMEM_GEMM);
    }

    // origin stream: memset, prep groups (recording an event after each), strip
    cudaMemsetAsync(out, 0, (size_t)out_size * sizeof(float));
    for (int g = 0; g < NGROUP; ++g) {
        prep_kernel<<<dim3(GBATCH, 2, 8), 256>>>(x1, x2, g * GBATCH);
        cudaEventRecord(evP[g], 0);
    }
    strip_kernel<<<dim3(BATCH, 4), 256>>>(out);

    // side stream: gemm group g gated on prep group g (memset ordered via evP edge)
    for (int g = 0; g < NGROUP; ++g) {
        cudaStreamWaitEvent(s1, evP[g], 0);
        gemm_kernel<<<GBATCH * 16, 256, SMEM_GEMM, s1>>>(out, g * GBATCH);
    }
    cudaEventRecord(evEnd, s1);
    cudaStreamWaitEvent(0, evEnd, 0);      // join back to origin stream
}

// round 15
// speedup vs baseline: 1.0953x; 1.0953x over previous
#include <cuda_runtime.h>
#include <cuda_fp16.h>
#include <cstdint>

// ======================= problem constants =======================
#define BATCH 64
#define WDIM  513
#define CDIM  512
#define PLANE_ELEMS (BATCH * WDIM * CDIM)   // 16,809,984

// fp16 planes of the L2-normalized inputs (scratch, ~67 MB)
__device__ __half g_h1[PLANE_ELEMS];
__device__ __half g_h2[PLANE_ELEMS];

// ======================= helpers =======================
__device__ __forceinline__ uint32_t smem_u32(const void* p) {
    uint32_t a;
    asm("{ .reg .u64 t; cvta.to.shared.u64 t, %1; cvt.u32.u64 %0, t; }" : "=r"(a) : "l"(p));
    return a;
}

#define CP_ASYNC16(dst, src) \
    asm volatile("cp.async.cg.shared.global [%0], [%1], 16;" :: "r"(dst), "l"(src) : "memory")
#define CP_COMMIT() asm volatile("cp.async.commit_group;" ::: "memory")
#define CP_WAIT(n)  asm volatile("cp.async.wait_group %0;" :: "n"(n) : "memory")

__device__ __forceinline__ void mma16816(float* d, uint32_t a0, uint32_t a1, uint32_t a2,
                                         uint32_t a3, uint32_t b0, uint32_t b1) {
    asm volatile(
        "mma.sync.aligned.m16n8k16.row.col.f32.f16.f16.f32 "
        "{%0,%1,%2,%3}, {%4,%5,%6,%7}, {%8,%9}, {%0,%1,%2,%3};"
        : "+f"(d[0]), "+f"(d[1]), "+f"(d[2]), "+f"(d[3])
        : "r"(a0), "r"(a1), "r"(a2), "r"(a3), "r"(b0), "r"(b1));
}

__device__ __forceinline__ void ldsm_x4(uint32_t* r, uint32_t addr) {
    asm volatile("ldmatrix.sync.aligned.m8n8.x4.shared.b16 {%0,%1,%2,%3}, [%4];"
                 : "=r"(r[0]), "=r"(r[1]), "=r"(r[2]), "=r"(r[3]) : "r"(addr));
}

// ======================= kernel 1: fused normalize + fp16 quantize =======================
// grid (64, 2, 8): batch, tensor, 64-channel block. 256 threads = 32 channel-pairs x 8 W-slices.
__global__ void __launch_bounds__(256) prep_kernel(const float* __restrict__ x1,
                                                   const float* __restrict__ x2) {
    __shared__ float2 red[8][32];
    __shared__ float2 sinv[32];
    const int b = blockIdx.x, which = blockIdx.y, cb = blockIdx.z;
    const float* in = which ? x2 : x1;
    __half* hp = which ? g_h2 : g_h1;

    const int cp = threadIdx.x & 31;          // channel pair within block
    const int sl = threadIdx.x >> 5;          // W slice (0..7)
    const int c  = (cb << 6) + (cp << 1);     // absolute channel (even)
    const int w0 = sl * 65;
    const int w1 = (w0 + 65 < WDIM) ? (w0 + 65) : WDIM;
    const size_t base = (size_t)b * WDIM * CDIM + c;

    float s0 = 0.0f, s1 = 0.0f;
    for (int w = w0; w < w1; ++w) {
        float2 v = *(const float2*)(in + base + (size_t)w * CDIM);
        s0 = fmaf(v.x, v.x, s0);
        s1 = fmaf(v.y, v.y, s1);
    }
    red[sl][cp] = make_float2(s0, s1);
    __syncthreads();
    if (threadIdx.x < 32) {
        float a0 = 0.0f, a1 = 0.0f;
#pragma unroll
        for (int s = 0; s < 8; ++s) { a0 += red[s][threadIdx.x].x; a1 += red[s][threadIdx.x].y; }
        sinv[threadIdx.x] = make_float2(rsqrtf(fmaxf(a0, 1e-12f)), rsqrtf(fmaxf(a1, 1e-12f)));
    }
    __syncthreads();
    const float2 iv = sinv[cp];

    for (int w = w0; w < w1; ++w) {
        const size_t idx = base + (size_t)w * CDIM;
        float2 v = *(const float2*)(in + idx);
        *(__half2*)(hp + idx) = __floats2half2_rn(v.x * iv.x, v.y * iv.y);
    }
}

// ======================= kernel 2: strips from fp16 planes (out pre-zeroed) ============
// grid (64, 4): batch, quarter. All contributions via atomicAdd.
__global__ void __launch_bounds__(256) strip_kernel(float* __restrict__ out) {
    __shared__ float2 p1v[256], p2v[256];
    const int b = blockIdx.x, qr = blockIdx.y;
    const int tid = threadIdx.x;
    const int wid = tid >> 5, lane = tid & 31;
    const size_t rbase = (size_t)b * WDIM * CDIM;

    p1v[tid] = __half22float2(((const __half2*)(g_h1 + rbase + (size_t)512 * CDIM))[tid]);
    p2v[tid] = __half22float2(((const __half2*)(g_h2 + rbase + (size_t)512 * CDIM))[tid]);
    __syncthreads();

    // part 1: j = 512 fixed:  out[(768-w') % 513] += <p1, x2n[w',:]>,  w' in quarter
    {
        const int w0 = qr * 129, w1 = (w0 + 129 < WDIM) ? (w0 + 129) : WDIM;
        for (int wp = w0 + wid; wp < w1; wp += 8) {
            const float4* row = (const float4*)(g_h2 + rbase + (size_t)wp * CDIM);
            float s = 0.0f;
#pragma unroll
            for (int k = 0; k < 2; ++k) {
                const int i = lane + (k << 5);          // float4 index (8 halves), 0..63
                float4 r4 = row[i];
                const __half2* h = (const __half2*)&r4;
#pragma unroll
                for (int j = 0; j < 4; ++j) {
                    float2 f = __half22float2(h[j]);
                    float2 p = p1v[i * 4 + j];
                    s = fmaf(f.x, p.x, fmaf(f.y, p.y, s));
                }
            }
            for (int o = 16; o; o >>= 1) s += __shfl_xor_sync(0xFFFFFFFFu, s, o);
            if (lane == 0) atomicAdd(&out[(size_t)b * WDIM + (768 - wp) % WDIM], s);
        }
    }
    // part 2: w' = 512 fixed:  out[(j+257) % 513] += <p2, x1n[j,:]>,  j in quarter (0..511)
    {
        const int j0 = qr * 128, j1 = j0 + 128;
        for (int j = j0 + wid; j < j1; j += 8) {
            const float4* row = (const float4*)(g_h1 + rbase + (size_t)j * CDIM);
            float s = 0.0f;
#pragma unroll
            for (int k = 0; k < 2; ++k) {
                const int i = lane + (k << 5);
                float4 r4 = row[i];
                const __half2* h = (const __half2*)&r4;
#pragma unroll
                for (int jj = 0; jj < 4; ++jj) {
                    float2 f = __half22float2(h[jj]);
                    float2 p = p2v[i * 4 + jj];
                    s = fmaf(f.x, p.x, fmaf(f.y, p.y, s));
                }
            }
            for (int o = 16; o; o >>= 1) s += __shfl_xor_sync(0xFFFFFFFFu, s, o);
            if (lane == 0) atomicAdd(&out[(size_t)b * WDIM + (j + 257) % WDIM], s);
        }
    }
}

// ======================= kernel 3: fp16 mma.sync GEMM, 128x64 CTA tiles ==========
// CTA: 128(M=j) x 64(N=w') Gram tile; K=512 in 8 chunks of 64 halves, 3-stage cp.async.
// 256 threads = 8 warps (4M x 2N), warp tile 32x32 -> ~75 regs -> 3 CTAs/SM.
// grid = 64 batches x 4 M-tiles x 8 N-tiles = 2048.
#define NCHUNKS  8                     // 512 / 64
#define STAGE    24576                 // A 16KB (128 rows) + B 8KB (64 rows), 128B/row
#define NSTAGE   3
#define CPITCH   66
#define SMEM_GEMM (NSTAGE * STAGE)     // 73728 >= epilogue 128*66*4 = 33792

__global__ void __launch_bounds__(256, 3) gemm_kernel(float* __restrict__ out) {
    extern __shared__ char sm[];
    const uint32_t sb = smem_u32(sm);

    const int tid  = threadIdx.x;
    const int lane = tid & 31, warp = tid >> 5;
    const int wm = warp >> 1, wn = warp & 1;       // warp grid 4(M) x 2(N)
    const int l15 = lane & 15;

    const int b  = blockIdx.x >> 5;
    const int j0 = ((blockIdx.x >> 3) & 3) << 7;
    const int n0 = (blockIdx.x & 7) << 6;

    float acc[2][4][4];
#pragma unroll
    for (int mt = 0; mt < 2; ++mt)
#pragma unroll
        for (int nt = 0; nt < 4; ++nt)
#pragma unroll
            for (int i = 0; i < 4; ++i) acc[mt][nt][i] = 0.0f;

    // O(1)-register loader bases (swizzle is q-invariant: row steps by 32 per q)
    const int lr = tid >> 3, lc = tid & 7;
    const uint32_t dOff0 = (uint32_t)((lr << 7) + ((lc ^ (lr & 7)) << 4));
    const uint32_t sOff0 = (uint32_t)(lr * CDIM + (lc << 3));
    const __half* pA = g_h1 + ((size_t)(b * WDIM + j0)) * CDIM + sOff0;
    const __half* pB = g_h2 + ((size_t)(b * WDIM + n0)) * CDIM + sOff0;

    // per-lane ldmatrix address components (row base * 128B + swizzled 16B chunk)
    uint32_t offk[4];
#pragma unroll
    for (int ks = 0; ks < 4; ++ks)
        offk[ks] = (uint32_t)((((ks << 1) | (lane >> 4)) ^ (lane & 7)) << 4);
    uint32_t arow[2], brow[2];
#pragma unroll
    for (int mt = 0; mt < 2; ++mt) arow[mt] = (uint32_t)((wm * 32 + mt * 16 + l15) << 7);
#pragma unroll
    for (int ng = 0; ng < 2; ++ng) brow[ng] = (uint32_t)((wn * 32 + ng * 16 + l15) << 7);

    // async chunk loader: 64 halves of K (128B/row), XOR-swizzled 16B chunks
    auto load_chunk = [&](int k, int s) {
        const uint32_t c0 = k << 6;
        const uint32_t sA = sb + s * STAGE + dOff0;
        const uint32_t sB = sA + 16384;
#pragma unroll
        for (int q = 0; q < 4; ++q) CP_ASYNC16(sA + q * 4096, pA + c0 + q * (32 * CDIM));
#pragma unroll
        for (int q = 0; q < 2; ++q) CP_ASYNC16(sB + q * 4096, pB + c0 + q * (32 * CDIM));
        CP_COMMIT();
    };

    load_chunk(0, 0);
    load_chunk(1, 1);

    int st = 0, ls = 2;
    for (int k = 0; k < NCHUNKS; ++k) {
        if (k < NCHUNKS - 1) { CP_WAIT(1); } else { CP_WAIT(0); }
        __syncthreads();
        if (k + 2 < NCHUNKS) load_chunk(k + 2, ls);

        const uint32_t sA = sb + st * STAGE;
        const uint32_t sB = sA + 16384;
#pragma unroll
        for (int ks = 0; ks < 4; ++ks) {
            uint32_t a0[4], a1[4];
            ldsm_x4(a0, sA + arow[0] + offk[ks]);
            ldsm_x4(a1, sA + arow[1] + offk[ks]);
#pragma unroll
            for (int ng = 0; ng < 2; ++ng) {
                uint32_t q[4];
                ldsm_x4(q, sB + brow[ng] + offk[ks]);
                mma16816(acc[0][ng * 2],     a0[0], a0[1], a0[2], a0[3], q[0], q[2]);
                mma16816(acc[0][ng * 2 + 1], a0[0], a0[1], a0[2], a0[3], q[1], q[3]);
                mma16816(acc[1][ng * 2],     a1[0], a1[1], a1[2], a1[3], q[0], q[2]);
                mma16816(acc[1][ng * 2 + 1], a1[0], a1[1], a1[2], a1[3], q[1], q[3]);
            }
        }
        st = (st == NSTAGE - 1) ? 0 : st + 1;
        ls = (ls == NSTAGE - 1) ? 0 : ls + 1;
    }

    // --- epilogue: stage C in smem, fold diagonals, atomicAdd to global ---
    __syncthreads();
    float* C = (float*)sm;
    const int g = lane >> 2, t4 = lane & 3;
#pragma unroll
    for (int mt = 0; mt < 2; ++mt) {
        const int r0 = wm * 32 + mt * 16 + g;
#pragma unroll
        for (int nt = 0; nt < 4; ++nt) {
            const int c = wn * 32 + nt * 8 + 2 * t4;
            C[r0 * CPITCH + c]           = acc[mt][nt][0];
            C[r0 * CPITCH + c + 1]       = acc[mt][nt][1];
            C[(r0 + 8) * CPITCH + c]     = acc[mt][nt][2];
            C[(r0 + 8) * CPITCH + c + 1] = acc[mt][nt][3];
        }
    }
    __syncthreads();

    if (tid < 191) {
        const int d = tid - 63;                  // diag offset r - c, -63..127
        float s = 0.0f;
#pragma unroll 4
        for (int r = 0; r < 128; ++r) {
            const int c = r - d;
            if (c >= 0 && c < 64) s += C[r * CPITCH + c];
        }
        const int widx = (j0 - n0 + d + 256 + 1026) % WDIM;
        atomicAdd(&out[(size_t)b * WDIM + widx], s);
    }
}

// ======================= launch =======================
extern "C" void kernel_launch(void* const* d_in, const int* in_sizes, int n_in,
                              void* d_out, int out_size) {
    const float* x1 = (const float*)d_in[0];
    const float* x2 = (const float*)d_in[1];
    float* out = (float*)d_out;

    cudaFuncSetAttribute(gemm_kernel, cudaFuncAttributeMaxDynamicSharedMemorySize, SMEM_GEMM);

    cudaMemsetAsync(d_out, 0, (size_t)out_size * sizeof(float));
    prep_kernel<<<dim3(BATCH, 2, 8), 256>>>(x1, x2);
    strip_kernel<<<dim3(BATCH, 4), 256>>>(out);
    gemm_kernel<<<BATCH * 32, 256, SMEM_GEMM>>>(out);
}

// round 16
// speedup vs baseline: 1.1384x; 1.0394x over previous
#include <cuda_runtime.h>
#include <cuda_fp16.h>
#include <cstdint>

// ======================= problem constants =======================
#define BATCH 64
#define WDIM  513
#define CDIM  512
#define PLANE_ELEMS (BATCH * WDIM * CDIM)   // 16,809,984

// fp16 planes of the L2-normalized inputs (scratch, ~67 MB)
__device__ __half g_h1[PLANE_ELEMS];
__device__ __half g_h2[PLANE_ELEMS];

// ======================= helpers =======================
__device__ __forceinline__ uint32_t smem_u32(const void* p) {
    uint32_t a;
    asm("{ .reg .u64 t; cvta.to.shared.u64 t, %1; cvt.u32.u64 %0, t; }" : "=r"(a) : "l"(p));
    return a;
}

#define CP_ASYNC16(dst, src) \
    asm volatile("cp.async.cg.shared.global [%0], [%1], 16;" :: "r"(dst), "l"(src) : "memory")
#define CP_COMMIT() asm volatile("cp.async.commit_group;" ::: "memory")
#define CP_WAIT(n)  asm volatile("cp.async.wait_group %0;" :: "n"(n) : "memory")

__device__ __forceinline__ void mma16816(float* d, uint32_t a0, uint32_t a1, uint32_t a2,
                                         uint32_t a3, uint32_t b0, uint32_t b1) {
    asm volatile(
        "mma.sync.aligned.m16n8k16.row.col.f32.f16.f16.f32 "
        "{%0,%1,%2,%3}, {%4,%5,%6,%7}, {%8,%9}, {%0,%1,%2,%3};"
        : "+f"(d[0]), "+f"(d[1]), "+f"(d[2]), "+f"(d[3])
        : "r"(a0), "r"(a1), "r"(a2), "r"(a3), "r"(b0), "r"(b1));
}

__device__ __forceinline__ void ldsm_x4(uint32_t* r, uint32_t addr) {
    asm volatile("ldmatrix.sync.aligned.m8n8.x4.shared.b16 {%0,%1,%2,%3}, [%4];"
                 : "=r"(r[0]), "=r"(r[1]), "=r"(r[2]), "=r"(r[3]) : "r"(addr));
}

// ======================= kernel 1: fused normalize + fp16 quantize =======================
// grid (64, 2, 8): batch, tensor, 64-channel block. 256 threads = 32 channel-pairs x 8 W-slices.
// Pass 2 runs in REVERSE W order (LIFO reuse of pass-1 cache lines) with last-use loads.
__global__ void __launch_bounds__(256) prep_kernel(const float* __restrict__ x1,
                                                   const float* __restrict__ x2) {
    __shared__ float2 red[8][32];
    __shared__ float2 sinv[32];
    const int b = blockIdx.x, which = blockIdx.y, cb = blockIdx.z;
    const float* in = which ? x2 : x1;
    __half* hp = which ? g_h2 : g_h1;

    const int cp = threadIdx.x & 31;          // channel pair within block
    const int sl = threadIdx.x >> 5;          // W slice (0..7)
    const int c  = (cb << 6) + (cp << 1);     // absolute channel (even)
    const int w0 = sl * 65;
    const int w1 = (w0 + 65 < WDIM) ? (w0 + 65) : WDIM;
    const size_t base = (size_t)b * WDIM * CDIM + c;

    float s0 = 0.0f, s1 = 0.0f;
    for (int w = w0; w < w1; ++w) {
        float2 v = *(const float2*)(in + base + (size_t)w * CDIM);
        s0 = fmaf(v.x, v.x, s0);
        s1 = fmaf(v.y, v.y, s1);
    }
    red[sl][cp] = make_float2(s0, s1);
    __syncthreads();
    if (threadIdx.x < 32) {
        float a0 = 0.0f, a1 = 0.0f;
#pragma unroll
        for (int s = 0; s < 8; ++s) { a0 += red[s][threadIdx.x].x; a1 += red[s][threadIdx.x].y; }
        sinv[threadIdx.x] = make_float2(rsqrtf(fmaxf(a0, 1e-12f)), rsqrtf(fmaxf(a1, 1e-12f)));
    }
    __syncthreads();
    const float2 iv = sinv[cp];

    // reverse order: most-recently-cached rows first; __ldlu = last use (evict early)
    for (int w = w1 - 1; w >= w0; --w) {
        const size_t idx = base + (size_t)w * CDIM;
        float2 v = __ldlu((const float2*)(in + idx));
        *(__half2*)(hp + idx) = __floats2half2_rn(v.x * iv.x, v.y * iv.y);
    }
}

// ======================= kernel 2: strips from fp16 planes (out pre-zeroed) ============
// grid (64, 4): batch, quarter. All contributions via atomicAdd.
__global__ void __launch_bounds__(256) strip_kernel(float* __restrict__ out) {
    __shared__ float2 p1v[256], p2v[256];
    const int b = blockIdx.x, qr = blockIdx.y;
    const int tid = threadIdx.x;
    const int wid = tid >> 5, lane = tid & 31;
    const size_t rbase = (size_t)b * WDIM * CDIM;

    p1v[tid] = __half22float2(((const __half2*)(g_h1 + rbase + (size_t)512 * CDIM))[tid]);
    p2v[tid] = __half22float2(((const __half2*)(g_h2 + rbase + (size_t)512 * CDIM))[tid]);
    __syncthreads();

    // part 1: j = 512 fixed:  out[(768-w') % 513] += <p1, x2n[w',:]>,  w' in quarter
    {
        const int w0 = qr * 129, w1 = (w0 + 129 < WDIM) ? (w0 + 129) : WDIM;
        for (int wp = w0 + wid; wp < w1; wp += 8) {
            const float4* row = (const float4*)(g_h2 + rbase + (size_t)wp * CDIM);
            float s = 0.0f;
#pragma unroll
            for (int k = 0; k < 2; ++k) {
                const int i = lane + (k << 5);          // float4 index (8 halves), 0..63
                float4 r4 = row[i];
                const __half2* h = (const __half2*)&r4;
#pragma unroll
                for (int j = 0; j < 4; ++j) {
                    float2 f = __half22float2(h[j]);
                    float2 p = p1v[i * 4 + j];
                    s = fmaf(f.x, p.x, fmaf(f.y, p.y, s));
                }
            }
            for (int o = 16; o; o >>= 1) s += __shfl_xor_sync(0xFFFFFFFFu, s, o);
            if (lane == 0) atomicAdd(&out[(size_t)b * WDIM + (768 - wp) % WDIM], s);
        }
    }
    // part 2: w' = 512 fixed:  out[(j+257) % 513] += <p2, x1n[j,:]>,  j in quarter (0..511)
    {
        const int j0 = qr * 128, j1 = j0 + 128;
        for (int j = j0 + wid; j < j1; j += 8) {
            const float4* row = (const float4*)(g_h1 + rbase + (size_t)j * CDIM);
            float s = 0.0f;
#pragma unroll
            for (int k = 0; k < 2; ++k) {
                const int i = lane + (k << 5);
                float4 r4 = row[i];
                const __half2* h = (const __half2*)&r4;
#pragma unroll
                for (int jj = 0; jj < 4; ++jj) {
                    float2 f = __half22float2(h[jj]);
                    float2 p = p2v[i * 4 + jj];
                    s = fmaf(f.x, p.x, fmaf(f.y, p.y, s));
                }
            }
            for (int o = 16; o; o >>= 1) s += __shfl_xor_sync(0xFFFFFFFFu, s, o);
            if (lane == 0) atomicAdd(&out[(size_t)b * WDIM + (j + 257) % WDIM], s);
        }
    }
}

// ======================= kernel 3: fp16 mma.sync GEMM, K = 512 (round-13 config) ========
// CTA: 128(M=j) x 128(N=w') Gram tile; 8 chunks of 64 halves, 3-stage cp.async.
// 256 threads = 8 warps (4M x 2N), warp tile 32x64 (smem:tensor co-balanced 1024:1024).
#define NCHUNKS  8                     // 512 / 64
#define STAGE    32768                 // A 16KB + B 16KB (128 rows x 128B each)
#define NSTAGE   3
#define CPITCH   130
#define SMEM_GEMM (NSTAGE * STAGE)     // 98304 >= epilogue 128*130*4 = 66560

__global__ void __launch_bounds__(256, 2) gemm_kernel(float* __restrict__ out) {
    extern __shared__ char sm[];
    const uint32_t sb = smem_u32(sm);

    const int tid  = threadIdx.x;
    const int lane = tid & 31, warp = tid >> 5;
    const int wm = warp >> 1, wn = warp & 1;       // warp grid 4(M) x 2(N)
    const int l15 = lane & 15;

    const int b  = blockIdx.x >> 4;
    const int j0 = ((blockIdx.x >> 2) & 3) << 7;
    const int n0 = (blockIdx.x & 3) << 7;

    float acc[2][8][4];
#pragma unroll
    for (int mt = 0; mt < 2; ++mt)
#pragma unroll
        for (int nt = 0; nt < 8; ++nt)
#pragma unroll
            for (int i = 0; i < 4; ++i) acc[mt][nt][i] = 0.0f;

    // O(1)-register loader bases (swizzle is q-invariant: row steps by 32 per q)
    const int lr = tid >> 3, lc = tid & 7;
    const uint32_t dOff0 = (uint32_t)((lr << 7) + ((lc ^ (lr & 7)) << 4));
    const uint32_t sOff0 = (uint32_t)(lr * CDIM + (lc << 3));
    const __half* pA = g_h1 + ((size_t)(b * WDIM + j0)) * CDIM + sOff0;
    const __half* pB = g_h2 + ((size_t)(b * WDIM + n0)) * CDIM + sOff0;

    // per-lane ldmatrix address components (row base * 128B + swizzled 16B chunk)
    uint32_t offk[4];
#pragma unroll
    for (int ks = 0; ks < 4; ++ks)
        offk[ks] = (uint32_t)((((ks << 1) | (lane >> 4)) ^ (lane & 7)) << 4);
    uint32_t arow[2], brow[4];
#pragma unroll
    for (int mt = 0; mt < 2; ++mt) arow[mt] = (uint32_t)((wm * 32 + mt * 16 + l15) << 7);
#pragma unroll
    for (int ng = 0; ng < 4; ++ng) brow[ng] = (uint32_t)((wn * 64 + ng * 16 + l15) << 7);

    // async chunk loader: 64 halves of K (128B/row), XOR-swizzled 16B chunks
    auto load_chunk = [&](int k, int s) {
        const uint32_t c0 = k << 6;
        const uint32_t sA = sb + s * STAGE + dOff0;
        const uint32_t sB = sA + 16384;
#pragma unroll
        for (int q = 0; q < 4; ++q) CP_ASYNC16(sA + q * 4096, pA + c0 + q * (32 * CDIM));
#pragma unroll
        for (int q = 0; q < 4; ++q) CP_ASYNC16(sB + q * 4096, pB + c0 + q * (32 * CDIM));
        CP_COMMIT();
    };

    load_chunk(0, 0);
    load_chunk(1, 1);

    int st = 0, ls = 2;
    for (int k = 0; k < NCHUNKS; ++k) {
        if (k < NCHUNKS - 1) { CP_WAIT(1); } else { CP_WAIT(0); }
        __syncthreads();
        if (k + 2 < NCHUNKS) load_chunk(k + 2, ls);

        const uint32_t sA = sb + st * STAGE;
        const uint32_t sB = sA + 16384;
#pragma unroll
        for (int ks = 0; ks < 4; ++ks) {
            uint32_t a0[4], a1[4];
            ldsm_x4(a0, sA + arow[0] + offk[ks]);
            ldsm_x4(a1, sA + arow[1] + offk[ks]);
#pragma unroll
            for (int ng = 0; ng < 4; ++ng) {
                uint32_t q[4];
                ldsm_x4(q, sB + brow[ng] + offk[ks]);
                mma16816(acc[0][ng * 2],     a0[0], a0[1], a0[2], a0[3], q[0], q[2]);
                mma16816(acc[0][ng * 2 + 1], a0[0], a0[1], a0[2], a0[3], q[1], q[3]);
                mma16816(acc[1][ng * 2],     a1[0], a1[1], a1[2], a1[3], q[0], q[2]);
                mma16816(acc[1][ng * 2 + 1], a1[0], a1[1], a1[2], a1[3], q[1], q[3]);
            }
        }
        st = (st == NSTAGE - 1) ? 0 : st + 1;
        ls = (ls == NSTAGE - 1) ? 0 : ls + 1;
    }

    // --- epilogue: stage C in smem, fold diagonals, atomicAdd to global ---
    __syncthreads();
    float* C = (float*)sm;
    const int g = lane >> 2, t4 = lane & 3;
#pragma unroll
    for (int mt = 0; mt < 2; ++mt) {
        const int r0 = wm * 32 + mt * 16 + g;
#pragma unroll
        for (int nt = 0; nt < 8; ++nt) {
            const int c = wn * 64 + nt * 8 + 2 * t4;
            C[r0 * CPITCH + c]           = acc[mt][nt][0];
            C[r0 * CPITCH + c + 1]       = acc[mt][nt][1];
            C[(r0 + 8) * CPITCH + c]     = acc[mt][nt][2];
            C[(r0 + 8) * CPITCH + c + 1] = acc[mt][nt][3];
        }
    }
    __syncthreads();

    if (tid < 255) {
        const int d = tid - 127;                 // diag offset r - c
        float s = 0.0f;
#pragma unroll 4
        for (int r = 0; r < 128; ++r) {
            const int c = r - d;
            if (c >= 0 && c < 128) s += C[r * CPITCH + c];
        }
        const int widx = (j0 - n0 + d + 256 + 1026) % WDIM;
        atomicAdd(&out[(size_t)b * WDIM + widx], s);
    }
}

// ======================= launch =======================
extern "C" void kernel_launch(void* const* d_in, const int* in_sizes, int n_in,
                              void* d_out, int out_size) {
    const float* x1 = (const float*)d_in[0];
    const float* x2 = (const float*)d_in[1];
    float* out = (float*)d_out;

    cudaFuncSetAttribute(gemm_kernel, cudaFuncAttributeMaxDynamicSharedMemorySize, SMEM_GEMM);

    cudaMemsetAsync(d_out, 0, (size_t)out_size * sizeof(float));
    prep_kernel<<<dim3(BATCH, 2, 8), 256>>>(x1, x2);
    strip_kernel<<<dim3(BATCH, 4), 256>>>(out);
    gemm_kernel<<<BATCH * 16, 256, SMEM_GEMM>>>(out);
}

// round 17
// speedup vs baseline: 1.1824x; 1.0387x over previous
#include <cuda_runtime.h>
#include <cuda_fp16.h>
#include <cstdint>

// ======================= problem constants =======================
#define BATCH 64
#define WDIM  513
#define CDIM  512
#define PLANE_ELEMS (BATCH * WDIM * CDIM)   // 16,809,984

// fp16 planes of the L2-normalized inputs (scratch, ~67 MB)
__device__ __half g_h1[PLANE_ELEMS];
__device__ __half g_h2[PLANE_ELEMS];

// ======================= helpers =======================
__device__ __forceinline__ uint32_t smem_u32(const void* p) {
    uint32_t a;
    asm("{ .reg .u64 t; cvta.to.shared.u64 t, %1; cvt.u32.u64 %0, t; }" : "=r"(a) : "l"(p));
    return a;
}

#define CP_ASYNC16(dst, src) \
    asm volatile("cp.async.cg.shared.global [%0], [%1], 16;" :: "r"(dst), "l"(src) : "memory")
#define CP_COMMIT() asm volatile("cp.async.commit_group;" ::: "memory")
#define CP_WAIT(n)  asm volatile("cp.async.wait_group %0;" :: "n"(n) : "memory")

__device__ __forceinline__ void mma16816(float* d, uint32_t a0, uint32_t a1, uint32_t a2,
                                         uint32_t a3, uint32_t b0, uint32_t b1) {
    asm volatile(
        "mma.sync.aligned.m16n8k16.row.col.f32.f16.f16.f32 "
        "{%0,%1,%2,%3}, {%4,%5,%6,%7}, {%8,%9}, {%0,%1,%2,%3};"
        : "+f"(d[0]), "+f"(d[1]), "+f"(d[2]), "+f"(d[3])
        : "r"(a0), "r"(a1), "r"(a2), "r"(a3), "r"(b0), "r"(b1));
}

__device__ __forceinline__ void ldsm_x4(uint32_t* r, uint32_t addr) {
    asm volatile("ldmatrix.sync.aligned.m8n8.x4.shared.b16 {%0,%1,%2,%3}, [%4];"
                 : "=r"(r[0]), "=r"(r[1]), "=r"(r[2]), "=r"(r[3]) : "r"(addr));
}

// ======================= kernel 1: fused normalize + fp16 quantize (float4-wide) =======
// grid (64, 2, 8): batch, tensor, 64-channel block. 256 threads = 16 channel-quads x 16 W-slices.
// Pass 2 runs in REVERSE W order (LIFO reuse of pass-1 cache lines) with last-use loads.
__global__ void __launch_bounds__(256) prep_kernel(const float* __restrict__ x1,
                                                   const float* __restrict__ x2) {
    __shared__ float4 red[16][17];            // pad 17: conflict-free column reads
    __shared__ float4 sinv[16];
    const int b = blockIdx.x, which = blockIdx.y, cb = blockIdx.z;
    const float* in = which ? x2 : x1;
    __half* hp = which ? g_h2 : g_h1;

    const int cq = threadIdx.x & 15;          // channel quad within block
    const int sl = threadIdx.x >> 4;          // W slice (0..15)
    const int c  = (cb << 6) + (cq << 2);     // absolute channel (multiple of 4)
    const int w0 = sl * 33;
    const int w1 = (w0 + 33 < WDIM) ? (w0 + 33) : WDIM;   // last slice: 18 rows
    const size_t base = (size_t)b * WDIM * CDIM + c;

    float4 s = make_float4(0.f, 0.f, 0.f, 0.f);
    for (int w = w0; w < w1; ++w) {
        float4 v = *(const float4*)(in + base + (size_t)w * CDIM);
        s.x = fmaf(v.x, v.x, s.x);
        s.y = fmaf(v.y, v.y, s.y);
        s.z = fmaf(v.z, v.z, s.z);
        s.w = fmaf(v.w, v.w, s.w);
    }
    red[sl][cq] = s;
    __syncthreads();
    if (threadIdx.x < 16) {
        float4 a = make_float4(0.f, 0.f, 0.f, 0.f);
#pragma unroll
        for (int t = 0; t < 16; ++t) {
            float4 r = red[t][threadIdx.x];
            a.x += r.x; a.y += r.y; a.z += r.z; a.w += r.w;
        }
        sinv[threadIdx.x] = make_float4(rsqrtf(fmaxf(a.x, 1e-12f)), rsqrtf(fmaxf(a.y, 1e-12f)),
                                        rsqrtf(fmaxf(a.z, 1e-12f)), rsqrtf(fmaxf(a.w, 1e-12f)));
    }
    __syncthreads();
    const float4 iv = sinv[cq];

    // reverse order: most-recently-cached rows first; __ldlu = last use (evict early)
    for (int w = w1 - 1; w >= w0; --w) {
        const size_t idx = base + (size_t)w * CDIM;
        float4 v = __ldlu((const float4*)(in + idx));
        __half2 h0 = __floats2half2_rn(v.x * iv.x, v.y * iv.y);
        __half2 h1 = __floats2half2_rn(v.z * iv.z, v.w * iv.w);
        uint2 u;
        u.x = *reinterpret_cast<uint32_t*>(&h0);
        u.y = *reinterpret_cast<uint32_t*>(&h1);
        *(uint2*)(hp + idx) = u;
    }
}

// ======================= kernel 2: strips from fp16 planes (out pre-zeroed) ============
// grid (64, 4): batch, quarter. All contributions via atomicAdd.
__global__ void __launch_bounds__(256) strip_kernel(float* __restrict__ out) {
    __shared__ float2 p1v[256], p2v[256];
    const int b = blockIdx.x, qr = blockIdx.y;
    const int tid = threadIdx.x;
    const int wid = tid >> 5, lane = tid & 31;
    const size_t rbase = (size_t)b * WDIM * CDIM;

    p1v[tid] = __half22float2(((const __half2*)(g_h1 + rbase + (size_t)512 * CDIM))[tid]);
    p2v[tid] = __half22float2(((const __half2*)(g_h2 + rbase + (size_t)512 * CDIM))[tid]);
    __syncthreads();

    // part 1: j = 512 fixed:  out[(768-w') % 513] += <p1, x2n[w',:]>,  w' in quarter
    {
        const int w0 = qr * 129, w1 = (w0 + 129 < WDIM) ? (w0 + 129) : WDIM;
        for (int wp = w0 + wid; wp < w1; wp += 8) {
            const float4* row = (const float4*)(g_h2 + rbase + (size_t)wp * CDIM);
            float s = 0.0f;
#pragma unroll
            for (int k = 0; k < 2; ++k) {
                const int i = lane + (k << 5);          // float4 index (8 halves), 0..63
                float4 r4 = row[i];
                const __half2* h = (const __half2*)&r4;
#pragma unroll
                for (int j = 0; j < 4; ++j) {
                    float2 f = __half22float2(h[j]);
                    float2 p = p1v[i * 4 + j];
                    s = fmaf(f.x, p.x, fmaf(f.y, p.y, s));
                }
            }
            for (int o = 16; o; o >>= 1) s += __shfl_xor_sync(0xFFFFFFFFu, s, o);
            if (lane == 0) atomicAdd(&out[(size_t)b * WDIM + (768 - wp) % WDIM], s);
        }
    }
    // part 2: w' = 512 fixed:  out[(j+257) % 513] += <p2, x1n[j,:]>,  j in quarter (0..511)
    {
        const int j0 = qr * 128, j1 = j0 + 128;
        for (int j = j0 + wid; j < j1; j += 8) {
            const float4* row = (const float4*)(g_h1 + rbase + (size_t)j * CDIM);
            float s = 0.0f;
#pragma unroll
            for (int k = 0; k < 2; ++k) {
                const int i = lane + (k << 5);
                float4 r4 = row[i];
                const __half2* h = (const __half2*)&r4;
#pragma unroll
                for (int jj = 0; jj < 4; ++jj) {
                    float2 f = __half22float2(h[jj]);
                    float2 p = p2v[i * 4 + jj];
                    s = fmaf(f.x, p.x, fmaf(f.y, p.y, s));
                }
            }
            for (int o = 16; o; o >>= 1) s += __shfl_xor_sync(0xFFFFFFFFu, s, o);
            if (lane == 0) atomicAdd(&out[(size_t)b * WDIM + (j + 257) % WDIM], s);
        }
    }
}

// ======================= kernel 3: fp16 mma.sync GEMM, K = 512 (round-13 config) ========
// CTA: 128(M=j) x 128(N=w') Gram tile; 8 chunks of 64 halves, 3-stage cp.async.
// 256 threads = 8 warps (4M x 2N), warp tile 32x64 (smem:tensor co-balanced 1024:1024).
#define NCHUNKS  8                     // 512 / 64
#define STAGE    32768                 // A 16KB + B 16KB (128 rows x 128B each)
#define NSTAGE   3
#define CPITCH   130
#define SMEM_GEMM (NSTAGE * STAGE)     // 98304 >= epilogue 128*130*4 = 66560

__global__ void __launch_bounds__(256, 2) gemm_kernel(float* __restrict__ out) {
    extern __shared__ char sm[];
    const uint32_t sb = smem_u32(sm);

    const int tid  = threadIdx.x;
    const int lane = tid & 31, warp = tid >> 5;
    const int wm = warp >> 1, wn = warp & 1;       // warp grid 4(M) x 2(N)
    const int l15 = lane & 15;

    const int b  = blockIdx.x >> 4;
    const int j0 = ((blockIdx.x >> 2) & 3) << 7;
    const int n0 = (blockIdx.x & 3) << 7;

    float acc[2][8][4];
#pragma unroll
    for (int mt = 0; mt < 2; ++mt)
#pragma unroll
        for (int nt = 0; nt < 8; ++nt)
#pragma unroll
            for (int i = 0; i < 4; ++i) acc[mt][nt][i] = 0.0f;

    // O(1)-register loader bases (swizzle is q-invariant: row steps by 32 per q)
    const int lr = tid >> 3, lc = tid & 7;
    const uint32_t dOff0 = (uint32_t)((lr << 7) + ((lc ^ (lr & 7)) << 4));
    const uint32_t sOff0 = (uint32_t)(lr * CDIM + (lc << 3));
    const __half* pA = g_h1 + ((size_t)(b * WDIM + j0)) * CDIM + sOff0;
    const __half* pB = g_h2 + ((size_t)(b * WDIM + n0)) * CDIM + sOff0;

    // per-lane ldmatrix address components (row base * 128B + swizzled 16B chunk)
    uint32_t offk[4];
#pragma unroll
    for (int ks = 0; ks < 4; ++ks)
        offk[ks] = (uint32_t)((((ks << 1) | (lane >> 4)) ^ (lane & 7)) << 4);
    uint32_t arow[2], brow[4];
#pragma unroll
    for (int mt = 0; mt < 2; ++mt) arow[mt] = (uint32_t)((wm * 32 + mt * 16 + l15) << 7);
#pragma unroll
    for (int ng = 0; ng < 4; ++ng) brow[ng] = (uint32_t)((wn * 64 + ng * 16 + l15) << 7);

    // async chunk loader: 64 halves of K (128B/row), XOR-swizzled 16B chunks
    auto load_chunk = [&](int k, int s) {
        const uint32_t c0 = k << 6;
        const uint32_t sA = sb + s * STAGE + dOff0;
        const uint32_t sB = sA + 16384;
#pragma unroll
        for (int q = 0; q < 4; ++q) CP_ASYNC16(sA + q * 4096, pA + c0 + q * (32 * CDIM));
#pragma unroll
        for (int q = 0; q < 4; ++q) CP_ASYNC16(sB + q * 4096, pB + c0 + q * (32 * CDIM));
        CP_COMMIT();
    };

    load_chunk(0, 0);
    load_chunk(1, 1);

    int st = 0, ls = 2;
    for (int k = 0; k < NCHUNKS; ++k) {
        if (k < NCHUNKS - 1) { CP_WAIT(1); } else { CP_WAIT(0); }
        __syncthreads();
        if (k + 2 < NCHUNKS) load_chunk(k + 2, ls);

        const uint32_t sA = sb + st * STAGE;
        const uint32_t sB = sA + 16384;
#pragma unroll
        for (int ks = 0; ks < 4; ++ks) {
            uint32_t a0[4], a1[4];
            ldsm_x4(a0, sA + arow[0] + offk[ks]);
            ldsm_x4(a1, sA + arow[1] + offk[ks]);
#pragma unroll
            for (int ng = 0; ng < 4; ++ng) {
                uint32_t q[4];
                ldsm_x4(q, sB + brow[ng] + offk[ks]);
                mma16816(acc[0][ng * 2],     a0[0], a0[1], a0[2], a0[3], q[0], q[2]);
                mma16816(acc[0][ng * 2 + 1], a0[0], a0[1], a0[2], a0[3], q[1], q[3]);
                mma16816(acc[1][ng * 2],     a1[0], a1[1], a1[2], a1[3], q[0], q[2]);
                mma16816(acc[1][ng * 2 + 1], a1[0], a1[1], a1[2], a1[3], q[1], q[3]);
            }
        }
        st = (st == NSTAGE - 1) ? 0 : st + 1;
        ls = (ls == NSTAGE - 1) ? 0 : ls + 1;
    }

    // --- epilogue: stage C in smem, fold diagonals, atomicAdd to global ---
    __syncthreads();
    float* C = (float*)sm;
    const int g = lane >> 2, t4 = lane & 3;
#pragma unroll
    for (int mt = 0; mt < 2; ++mt) {
        const int r0 = wm * 32 + mt * 16 + g;
#pragma unroll
        for (int nt = 0; nt < 8; ++nt) {
            const int c = wn * 64 + nt * 8 + 2 * t4;
            C[r0 * CPITCH + c]           = acc[mt][nt][0];
            C[r0 * CPITCH + c + 1]       = acc[mt][nt][1];
            C[(r0 + 8) * CPITCH + c]     = acc[mt][nt][2];
            C[(r0 + 8) * CPITCH + c + 1] = acc[mt][nt][3];
        }
    }
    __syncthreads();

    if (tid < 255) {
        const int d = tid - 127;                 // diag offset r - c
        float s = 0.0f;
#pragma unroll 4
        for (int r = 0; r < 128; ++r) {
            const int c = r - d;
            if (c >= 0 && c < 128) s += C[r * CPITCH + c];
        }
        const int widx = (j0 - n0 + d + 256 + 1026) % WDIM;
        atomicAdd(&out[(size_t)b * WDIM + widx], s);
    }
}

// ======================= launch =======================
extern "C" void kernel_launch(void* const* d_in, const int* in_sizes, int n_in,
                              void* d_out, int out_size) {
    const float* x1 = (const float*)d_in[0];
    const float* x2 = (const float*)d_in[1];
    float* out = (float*)d_out;

    cudaFuncSetAttribute(gemm_kernel, cudaFuncAttributeMaxDynamicSharedMemorySize, SMEM_GEMM);

    cudaMemsetAsync(d_out, 0, (size_t)out_size * sizeof(float));
    prep_kernel<<<dim3(BATCH, 2, 8), 256>>>(x1, x2);
    strip_kernel<<<dim3(BATCH, 4), 256>>>(out);
    gemm_kernel<<<BATCH * 16, 256, SMEM_GEMM>>>(out);
}